// round 9
// baseline (speedup 1.0000x reference)
#include <cuda_runtime.h>
#include <cuda_bf16.h>
#include <cstdint>

#define N 4096
#define D 256
#define MARGIN 0.2f

#define BM 128
#define BN 128
#define BK 64
#define KTOT 768            // 3 segments x 256
#define NCHUNKS (KTOT / BK) // 12
#define ROWB 144            // padded smem row bytes (64 bf16 = 128B + 16B pad)
#define NTILE (N / BM)      // 32
#define NCTAS (NTILE * (NTILE + 1) / 2)  // 528

#define TILE_BYTES (BM * ROWB)           // 18432
#define DYN_SMEM (4 * TILE_BYTES)        // sA[2] + sB[2] = 73728

// ---------------- scratch (static device globals) ----------------
__device__ unsigned long long g_hp[N];   // (d2_bits<<32)|~idx, argmax (tie -> min idx)
__device__ unsigned long long g_hn[N];   // (d2_bits<<32)| idx, argmin (tie -> min idx)
__device__ float g_sq[N];
__device__ float g_loss[N];
__device__ int   g_nz[N];
__device__ unsigned short g_lab[N];      // class representative per row
__device__ __nv_bfloat16 g_Ehi[N * D];
__device__ __nv_bfloat16 g_Elo[N * D];

__device__ __forceinline__ unsigned long long pack_p(float v, int idx) {
    return (((unsigned long long)__float_as_uint(v)) << 32) | (unsigned)(~idx);
}
__device__ __forceinline__ unsigned long long pack_n(float v, int idx) {
    return (((unsigned long long)__float_as_uint(v)) << 32) | (unsigned)idx;
}

// ---------------- generic-PTX helpers (compute_103-safe) ----------------
__device__ __forceinline__ uint32_t smem_u32(const void* p) {
    uint32_t a;
    asm("{ .reg .u64 t; cvta.to.shared.u64 t, %1; cvt.u32.u64 %0, t; }" : "=r"(a) : "l"(p));
    return a;
}
__device__ __forceinline__ void cp16(uint32_t dst, const void* src) {
    asm volatile("cp.async.cg.shared.global [%0], [%1], 16;" :: "r"(dst), "l"(src));
}
#define CP_COMMIT() asm volatile("cp.async.commit_group;" ::: "memory")
#define CP_WAIT(n)  asm volatile("cp.async.wait_group %0;" :: "n"(n) : "memory")

__device__ __forceinline__ void ldm_x4(uint32_t& r0, uint32_t& r1, uint32_t& r2, uint32_t& r3,
                                       uint32_t addr) {
    asm volatile("ldmatrix.sync.aligned.m8n8.x4.shared.b16 {%0,%1,%2,%3}, [%4];"
                 : "=r"(r0), "=r"(r1), "=r"(r2), "=r"(r3) : "r"(addr));
}
__device__ __forceinline__ void mma_bf16(float* c, const uint32_t* a, const uint32_t* b) {
    asm volatile("mma.sync.aligned.m16n8k16.row.col.f32.bf16.bf16.f32 "
                 "{%0,%1,%2,%3}, {%4,%5,%6,%7}, {%8,%9}, {%0,%1,%2,%3};"
                 : "+f"(c[0]), "+f"(c[1]), "+f"(c[2]), "+f"(c[3])
                 : "r"(a[0]), "r"(a[1]), "r"(a[2]), "r"(a[3]), "r"(b[0]), "r"(b[1]));
}

// -------- kernel L: reconstruct class representatives from positives_mask ---
// Masks are label-derived (pos = same&~eye, neg = ~same), so pos is an
// equivalence relation minus the diagonal. rep[i] = min(i, first j with
// pos[i][j]) resolves to the minimum member of i's class for every member.
// Then pos(i,j) == (rep[i]==rep[j] && i!=j), neg(i,j) == (rep[i]!=rep[j]).
__global__ void k_labels(const unsigned char* __restrict__ pm,
                         const unsigned char* __restrict__ nm) {
    // dtype probe: element (0,1) is set in exactly one of pos/neg. u8 layout ->
    // byte 1 nonzero in one; i32 layout -> byte 1 is a zero high-byte in both.
    const bool is_u8 = ((pm[1] | nm[1]) != 0);
    int row = (blockIdx.x * blockDim.x + threadIdx.x) >> 5;
    int lane = threadIdx.x & 31;
    if (row >= N) return;
    int first = N;
    if (is_u8) {
        const unsigned char* prow = pm + (size_t)row * N;
        for (int base = 0; base < N; base += 32) {
            unsigned m = __ballot_sync(0xffffffffu, prow[base + lane] != 0);
            if (m) { first = base + __ffs(m) - 1; break; }
        }
    } else {
        const int* prow = (const int*)pm + (size_t)row * N;
        for (int base = 0; base < N; base += 32) {
            unsigned m = __ballot_sync(0xffffffffu, prow[base + lane] != 0);
            if (m) { first = base + __ffs(m) - 1; break; }
        }
    }
    if (lane == 0) g_lab[row] = (unsigned short)min(row, first);
}

// -------- kernel R: bf16 split + sq norms + scratch init (one pass) ---------
__global__ void k_prep(const float* __restrict__ E) {
    int warp = (blockIdx.x * blockDim.x + threadIdx.x) >> 5;
    int lane = threadIdx.x & 31;
    if (warp >= N) return;
    const float* row = E + (size_t)warp * D;
    __nv_bfloat16* hiRow = g_Ehi + (size_t)warp * D;
    __nv_bfloat16* loRow = g_Elo + (size_t)warp * D;
    float acc = 0.f;
#pragma unroll
    for (int t = 0; t < D / 32; ++t) {
        float v = row[lane + 32 * t];
        __nv_bfloat16 hi = __float2bfloat16(v);
        __nv_bfloat16 lo = __float2bfloat16(v - __bfloat162float(hi));
        hiRow[lane + 32 * t] = hi;
        loRow[lane + 32 * t] = lo;
        acc = fmaf(v, v, acc);
    }
#pragma unroll
    for (int o = 16; o; o >>= 1) acc += __shfl_xor_sync(0xffffffffu, acc, o);
    if (lane == 0) {
        g_sq[warp] = acc;
        g_hp[warp] = 0ULL;
        g_hn[warp] = 0xFFFFFFFFFFFFFFFFULL;
    }
}

// -------- kernel 1: bf16-split HMMA Gram tile + symmetric label mining ------
// 528 CTAs: upper-triangular tiles (bx<=by). Each computes the 128x128 Gram
// tile and mines BOTH orientations (d2 and the label relation are symmetric).
// sA/sB live in dynamic smem (73.7 KB): [sA0 | sA1 | sB0 | sB1].
__global__ void __launch_bounds__(256, 2) k_mine_mma() {
    extern __shared__ __align__(16) char dsm[];
    __shared__ float sRS[BM];
    __shared__ float sCSn[BN];
    __shared__ unsigned short sRL[BM];
    __shared__ unsigned short sCL[BN];
    __shared__ unsigned long long sBP[BM];
    __shared__ unsigned long long sBN[BM];

    const int tid = threadIdx.x;
    const int wid = tid >> 5;
    const int lane = tid & 31;
    const int warpRow = wid >> 2;        // 0..1  (64 rows each)
    const int warpCol = wid & 3;         // 0..3  (32 cols each)

    // triangular tile decode: tile t -> (bx, by), by >= bx
    int bx = 0, rem = blockIdx.x;
    while (rem >= NTILE - bx) { rem -= NTILE - bx; ++bx; }
    const int by = bx + rem;
    const int rowBase = bx * BM;
    const int colBase = by * BN;
    const bool offDiag = (bx != by);

    if (tid < BM) {
        sRS[tid]  = g_sq[rowBase + tid];
        sCSn[tid] = g_sq[colBase + tid];
        sRL[tid]  = g_lab[rowBase + tid];
        sCL[tid]  = g_lab[colBase + tid];
        sBP[tid]  = 0ULL;
        sBN[tid]  = 0xFFFFFFFFFFFFFFFFULL;
    }

    const uint32_t dynBase = smem_u32(dsm);
    const uint32_t aBase0 = dynBase;
    const uint32_t aBase1 = dynBase + TILE_BYTES;
    const uint32_t bBase0 = dynBase + 2 * TILE_BYTES;
    const uint32_t bBase1 = dynBase + 3 * TILE_BYTES;

    const __nv_bfloat16* srcA[3] = {g_Ehi, g_Ehi, g_Elo};
    const __nv_bfloat16* srcB[3] = {g_Ehi, g_Elo, g_Ehi};

    const int ldRow0 = tid >> 1;          // 2 threads per 128B row
    const int ldC0   = (tid & 1) * 4;     // each thread: 4 x 16B units

    float acc[4][4][4];
#pragma unroll
    for (int mi = 0; mi < 4; ++mi)
#pragma unroll
        for (int ni = 0; ni < 4; ++ni)
#pragma unroll
            for (int f = 0; f < 4; ++f) acc[mi][ni][f] = 0.f;

    auto loadChunk = [&](int kk, int stage) {
        int s  = kk >> 2;                 // segment (4 chunks of 64 each)
        int ko = (kk & 3) * BK;
        const __nv_bfloat16* A = srcA[s];
        const __nv_bfloat16* B = srcB[s];
        uint32_t aB = stage ? aBase1 : aBase0;
        uint32_t bB = stage ? bBase1 : bBase0;
#pragma unroll
        for (int i = 0; i < 4; ++i) {
            int c16 = ldC0 + i;           // 0..7
            cp16(aB + ldRow0 * ROWB + c16 * 16,
                 A + (size_t)(rowBase + ldRow0) * D + ko + c16 * 8);
            cp16(bB + ldRow0 * ROWB + c16 * 16,
                 B + (size_t)(colBase + ldRow0) * D + ko + c16 * 8);
        }
        CP_COMMIT();
    };

    loadChunk(0, 0);

    for (int kk = 0; kk < NCHUNKS; ++kk) {
        const int stage = kk & 1;
        if (kk + 1 < NCHUNKS) {
            loadChunk(kk + 1, stage ^ 1);
            CP_WAIT(1);
        } else {
            CP_WAIT(0);
        }
        __syncthreads();

        const uint32_t aB = stage ? aBase1 : aBase0;
        const uint32_t bB = stage ? bBase1 : bBase0;

#pragma unroll
        for (int kh = 0; kh < BK; kh += 16) {
            uint32_t af[4][4];
#pragma unroll
            for (int mi = 0; mi < 4; ++mi) {
                int row = warpRow * 64 + mi * 16 + (lane & 15);
                int col = kh + ((lane >> 4) & 1) * 8;
                ldm_x4(af[mi][0], af[mi][1], af[mi][2], af[mi][3],
                       aB + row * ROWB + col * 2);
            }
            uint32_t bf[4][2];
#pragma unroll
            for (int pn = 0; pn < 2; ++pn) {
                int ntile = 2 * pn + ((lane >> 4) & 1);
                int krel  = kh + ((lane >> 3) & 1) * 8;
                int rowb  = warpCol * 32 + ntile * 8 + (lane & 7);
                uint32_t r0, r1, r2, r3;
                ldm_x4(r0, r1, r2, r3, bB + rowb * ROWB + krel * 2);
                bf[2 * pn][0] = r0; bf[2 * pn][1] = r1;
                bf[2 * pn + 1][0] = r2; bf[2 * pn + 1][1] = r3;
            }
#pragma unroll
            for (int mi = 0; mi < 4; ++mi)
#pragma unroll
                for (int ni = 0; ni < 4; ++ni)
                    mma_bf16(acc[mi][ni], af[mi], bf[ni]);
        }
        __syncthreads();
    }

    const int l4 = lane >> 2;   // 0..7 : row-in-8
    const int l2 = lane & 3;    // 0..3 : col pair

    // ---- phase 1: row-anchor mining (anchors = rowBase block) ----
    {
#pragma unroll
        for (int mi = 0; mi < 4; ++mi) {
#pragma unroll
            for (int h = 0; h < 2; ++h) {
                const int rloc = warpRow * 64 + mi * 16 + l4 + 8 * h;
                const int grow = rowBase + rloc;
                const float rs = sRS[rloc];
                const unsigned rl = sRL[rloc];
                unsigned long long bp = 0ULL, bn = 0xFFFFFFFFFFFFFFFFULL;
#pragma unroll
                for (int ni = 0; ni < 4; ++ni) {
#pragma unroll
                    for (int cc = 0; cc < 2; ++cc) {
                        const int cloc = warpCol * 32 + ni * 8 + 2 * l2 + cc;
                        const int gcol = colBase + cloc;
                        const unsigned cl = sCL[cloc];
                        float d2 = fmaxf(rs + sCSn[cloc]
                                         - 2.0f * acc[mi][ni][2 * h + cc], 0.0f);
                        if (rl == cl) {
                            if (grow != gcol) {
                                unsigned long long c = pack_p(d2, gcol);
                                if (c > bp) bp = c;
                            }
                        } else {
                            unsigned long long c = pack_n(d2, gcol);
                            if (c < bn) bn = c;
                        }
                    }
                }
#pragma unroll
                for (int o = 1; o <= 2; o <<= 1) {
                    unsigned long long op = __shfl_xor_sync(0xffffffffu, bp, o);
                    if (op > bp) bp = op;
                    unsigned long long on = __shfl_xor_sync(0xffffffffu, bn, o);
                    if (on < bn) bn = on;
                }
                if (l2 == 0) {
                    if (bp != 0ULL) atomicMax(&sBP[rloc], bp);
                    if (bn != 0xFFFFFFFFFFFFFFFFULL) atomicMin(&sBN[rloc], bn);
                }
            }
        }
        __syncthreads();
        if (tid < BM) {
            if (sBP[tid] != 0ULL) atomicMax(&g_hp[rowBase + tid], sBP[tid]);
            if (sBN[tid] != 0xFFFFFFFFFFFFFFFFULL) atomicMin(&g_hn[rowBase + tid], sBN[tid]);
        }
    }

    // ---- phase 2: col-anchor mining (anchors = colBase block), off-diag only
    if (offDiag) {
        __syncthreads();
        if (tid < BM) {
            sBP[tid] = 0ULL;
            sBN[tid] = 0xFFFFFFFFFFFFFFFFULL;
        }
        __syncthreads();

#pragma unroll
        for (int ni = 0; ni < 4; ++ni) {
#pragma unroll
            for (int cc = 0; cc < 2; ++cc) {
                const int cloc = warpCol * 32 + ni * 8 + 2 * l2 + cc;
                const float cs = sCSn[cloc];
                const unsigned cl = sCL[cloc];
                unsigned long long bp = 0ULL, bn = 0xFFFFFFFFFFFFFFFFULL;
#pragma unroll
                for (int mi = 0; mi < 4; ++mi) {
#pragma unroll
                    for (int h = 0; h < 2; ++h) {
                        const int rloc = warpRow * 64 + mi * 16 + l4 + 8 * h;
                        const int grow = rowBase + rloc;
                        const unsigned rl = sRL[rloc];
                        float d2 = fmaxf(cs + sRS[rloc]
                                         - 2.0f * acc[mi][ni][2 * h + cc], 0.0f);
                        if (cl == rl) {
                            // off-diagonal tile => grow != gcol always
                            unsigned long long c = pack_p(d2, grow);
                            if (c > bp) bp = c;
                        } else {
                            unsigned long long c = pack_n(d2, grow);
                            if (c < bn) bn = c;
                        }
                    }
                }
                // merge the 8 lanes sharing this col (lane bits 2..4)
#pragma unroll
                for (int o = 4; o <= 16; o <<= 1) {
                    unsigned long long op = __shfl_xor_sync(0xffffffffu, bp, o);
                    if (op > bp) bp = op;
                    unsigned long long on = __shfl_xor_sync(0xffffffffu, bn, o);
                    if (on < bn) bn = on;
                }
                if (l4 == 0) {
                    if (bp != 0ULL) atomicMax(&sBP[cloc], bp);
                    if (bn != 0xFFFFFFFFFFFFFFFFULL) atomicMin(&sBN[cloc], bn);
                }
            }
        }
        __syncthreads();
        if (tid < BM) {
            if (sBP[tid] != 0ULL) atomicMax(&g_hp[colBase + tid], sBP[tid]);
            if (sBN[tid] != 0xFFFFFFFFFFFFFFFFULL) atomicMin(&g_hn[colBase + tid], sBN[tid]);
        }
    }
}

// -------- kernel 2: per-anchor d_pn + triplet loss --------------------------
__global__ void k_loss(const float* __restrict__ E) {
    int warp = (blockIdx.x * blockDim.x + threadIdx.x) >> 5;
    int lane = threadIdx.x & 31;
    if (warp >= N) return;
    int i = warp;
    unsigned long long hp = g_hp[i], hn = g_hn[i];
    bool valid = (hp != 0ULL) && (hn != 0xFFFFFFFFFFFFFFFFULL);
    if (!valid) {
        if (lane == 0) { g_loss[i] = 0.f; g_nz[i] = 0; }
        return;
    }
    int   pi   = (int)(~(unsigned)hp) & (N - 1);
    float d2ap = __uint_as_float((unsigned)(hp >> 32));
    int   ni   = (int)((unsigned)hn);
    float d2an = __uint_as_float((unsigned)(hn >> 32));

    const float* P = E + (size_t)pi * D;
    const float* Q = E + (size_t)ni * D;
    float acc = 0.f;
#pragma unroll
    for (int t = 0; t < D / 32; ++t)
        acc = fmaf(P[lane + 32 * t], Q[lane + 32 * t], acc);
#pragma unroll
    for (int o = 16; o; o >>= 1) acc += __shfl_xor_sync(0xffffffffu, acc, o);

    if (lane == 0) {
        float d2pn = fmaxf(g_sq[pi] + g_sq[ni] - 2.0f * acc, 0.0f);
        float l = fmaxf(sqrtf(d2ap) - fminf(sqrtf(d2an), sqrtf(d2pn)) + MARGIN, 0.0f);
        bool nz = l > 0.0f;
        g_loss[i] = nz ? l : 0.0f;
        g_nz[i]   = nz ? 1 : 0;
    }
}

// -------- kernel 3: deterministic final reduction ---------------------------
__global__ void k_reduce(float* __restrict__ out) {
    __shared__ float ssum[256];
    __shared__ int   scnt[256];
    int tid = threadIdx.x;
    float s = 0.f; int c = 0;
    for (int i = tid; i < N; i += 256) { s += g_loss[i]; c += g_nz[i]; }
    ssum[tid] = s; scnt[tid] = c;
    __syncthreads();
    for (int o = 128; o; o >>= 1) {
        if (tid < o) { ssum[tid] += ssum[tid + o]; scnt[tid] += scnt[tid + o]; }
        __syncthreads();
    }
    if (tid == 0) {
        float cnt = (float)scnt[0];
        out[0] = (cnt > 0.f) ? (ssum[0] / fmaxf(cnt, 1.0f)) : 0.0f;
    }
}

extern "C" void kernel_launch(void* const* d_in, const int* in_sizes, int n_in,
                              void* d_out, int out_size) {
    const float* E  = (const float*)d_in[0];
    const unsigned char* pm = (const unsigned char*)d_in[1];
    const unsigned char* nm = (const unsigned char*)d_in[2];
    float* out = (float*)d_out;

    // idempotent, not a stream op — safe under graph capture
    cudaFuncSetAttribute(k_mine_mma, cudaFuncAttributeMaxDynamicSharedMemorySize, DYN_SMEM);

    k_labels<<<N / 8, 256>>>(pm, nm);
    k_prep<<<N / 8, 256>>>(E);
    k_mine_mma<<<NCTAS, 256, DYN_SMEM>>>();
    k_loss<<<N / 8, 256>>>(E);
    k_reduce<<<1, 256>>>(out);
}

// round 10
// speedup vs baseline: 1.1095x; 1.1095x over previous
#include <cuda_runtime.h>
#include <cuda_bf16.h>
#include <cstdint>

#define N 4096
#define D 256
#define MARGIN 0.2f

#define BM 128
#define BN 128
#define BK 32
#define KTOT 768            // 3 segments x 256
#define NCHUNKS (KTOT / BK) // 24
#define ROWB 80             // padded smem row bytes (32 bf16 = 64B + 16B pad)
#define NSTAGE 3
#define NTILE (N / BM)      // 32
#define NCTAS (NTILE * (NTILE + 1) / 2)  // 528

#define TILE_BYTES (BM * ROWB)               // 10240
#define DYN_SMEM (2 * NSTAGE * TILE_BYTES)   // 61440

// ---------------- scratch (static device globals) ----------------
__device__ unsigned long long g_hp[N];   // (d2_bits<<32)|~idx, argmax (tie -> min idx)
__device__ unsigned long long g_hn[N];   // (d2_bits<<32)| idx, argmin (tie -> min idx)
__device__ float g_sq[N];
__device__ float g_loss[N];
__device__ int   g_nz[N];
__device__ unsigned short g_lab[N];      // class representative per row
__device__ __nv_bfloat16 g_Ehi[N * D];
__device__ __nv_bfloat16 g_Elo[N * D];

__device__ __forceinline__ unsigned long long pack_p(float v, int idx) {
    return (((unsigned long long)__float_as_uint(v)) << 32) | (unsigned)(~idx);
}
__device__ __forceinline__ unsigned long long pack_n(float v, int idx) {
    return (((unsigned long long)__float_as_uint(v)) << 32) | (unsigned)idx;
}

// ---------------- generic-PTX helpers (compute_103-safe) ----------------
__device__ __forceinline__ uint32_t smem_u32(const void* p) {
    uint32_t a;
    asm("{ .reg .u64 t; cvta.to.shared.u64 t, %1; cvt.u32.u64 %0, t; }" : "=r"(a) : "l"(p));
    return a;
}
__device__ __forceinline__ void cp16(uint32_t dst, const void* src) {
    asm volatile("cp.async.cg.shared.global [%0], [%1], 16;" :: "r"(dst), "l"(src));
}
#define CP_COMMIT() asm volatile("cp.async.commit_group;" ::: "memory")
#define CP_WAIT(n)  asm volatile("cp.async.wait_group %0;" :: "n"(n) : "memory")

__device__ __forceinline__ void ldm_x4(uint32_t& r0, uint32_t& r1, uint32_t& r2, uint32_t& r3,
                                       uint32_t addr) {
    asm volatile("ldmatrix.sync.aligned.m8n8.x4.shared.b16 {%0,%1,%2,%3}, [%4];"
                 : "=r"(r0), "=r"(r1), "=r"(r2), "=r"(r3) : "r"(addr));
}
__device__ __forceinline__ void mma_bf16(float* c, const uint32_t* a, const uint32_t* b) {
    asm volatile("mma.sync.aligned.m16n8k16.row.col.f32.bf16.bf16.f32 "
                 "{%0,%1,%2,%3}, {%4,%5,%6,%7}, {%8,%9}, {%0,%1,%2,%3};"
                 : "+f"(c[0]), "+f"(c[1]), "+f"(c[2]), "+f"(c[3])
                 : "r"(a[0]), "r"(a[1]), "r"(a[2]), "r"(a[3]), "r"(b[0]), "r"(b[1]));
}

// -------- kernel L: reconstruct class representatives from positives_mask ---
// Masks are label-derived (pos = same&~eye, neg = ~same), so pos is an
// equivalence relation minus the diagonal. rep[i] = min(i, first j with
// pos[i][j]) resolves to the minimum member of i's class for every member.
// Then pos(i,j) == (rep[i]==rep[j] && i!=j), neg(i,j) == (rep[i]!=rep[j]).
__global__ void k_labels(const unsigned char* __restrict__ pm,
                         const unsigned char* __restrict__ nm) {
    // dtype probe: element (0,1) is set in exactly one of pos/neg. u8 layout ->
    // byte 1 nonzero in one; i32 layout -> byte 1 is a zero high-byte in both.
    const bool is_u8 = ((pm[1] | nm[1]) != 0);
    int row = (blockIdx.x * blockDim.x + threadIdx.x) >> 5;
    int lane = threadIdx.x & 31;
    if (row >= N) return;
    int first = N;
    if (is_u8) {
        const unsigned char* prow = pm + (size_t)row * N;
        for (int base = 0; base < N; base += 32) {
            unsigned m = __ballot_sync(0xffffffffu, prow[base + lane] != 0);
            if (m) { first = base + __ffs(m) - 1; break; }
        }
    } else {
        const int* prow = (const int*)pm + (size_t)row * N;
        for (int base = 0; base < N; base += 32) {
            unsigned m = __ballot_sync(0xffffffffu, prow[base + lane] != 0);
            if (m) { first = base + __ffs(m) - 1; break; }
        }
    }
    if (lane == 0) g_lab[row] = (unsigned short)min(row, first);
}

// -------- kernel R: bf16 split + sq norms + scratch init (one pass) ---------
__global__ void k_prep(const float* __restrict__ E) {
    int warp = (blockIdx.x * blockDim.x + threadIdx.x) >> 5;
    int lane = threadIdx.x & 31;
    if (warp >= N) return;
    const float* row = E + (size_t)warp * D;
    __nv_bfloat16* hiRow = g_Ehi + (size_t)warp * D;
    __nv_bfloat16* loRow = g_Elo + (size_t)warp * D;
    float acc = 0.f;
#pragma unroll
    for (int t = 0; t < D / 32; ++t) {
        float v = row[lane + 32 * t];
        __nv_bfloat16 hi = __float2bfloat16(v);
        __nv_bfloat16 lo = __float2bfloat16(v - __bfloat162float(hi));
        hiRow[lane + 32 * t] = hi;
        loRow[lane + 32 * t] = lo;
        acc = fmaf(v, v, acc);
    }
#pragma unroll
    for (int o = 16; o; o >>= 1) acc += __shfl_xor_sync(0xffffffffu, acc, o);
    if (lane == 0) {
        g_sq[warp] = acc;
        g_hp[warp] = 0ULL;
        g_hn[warp] = 0xFFFFFFFFFFFFFFFFULL;
    }
}

// -------- kernel 1: bf16-split HMMA Gram tile + symmetric label mining ------
// 528 CTAs: upper-triangular tiles (bx<=by). 3-stage cp.async pipeline with a
// single __syncthreads per chunk. Dyn smem: [A0|A1|A2|B0|B1|B2].
__global__ void __launch_bounds__(256, 2) k_mine_mma() {
    extern __shared__ __align__(16) char dsm[];
    __shared__ float sRS[BM];
    __shared__ float sCSn[BN];
    __shared__ unsigned short sRL[BM];
    __shared__ unsigned short sCL[BN];
    __shared__ unsigned long long sBP[BM];
    __shared__ unsigned long long sBN[BM];

    const int tid = threadIdx.x;
    const int wid = tid >> 5;
    const int lane = tid & 31;
    const int warpRow = wid >> 2;        // 0..1  (64 rows each)
    const int warpCol = wid & 3;         // 0..3  (32 cols each)

    // triangular tile decode: tile t -> (bx, by), by >= bx
    int bx = 0, rem = blockIdx.x;
    while (rem >= NTILE - bx) { rem -= NTILE - bx; ++bx; }
    const int by = bx + rem;
    const int rowBase = bx * BM;
    const int colBase = by * BN;
    const bool offDiag = (bx != by);

    if (tid < BM) {
        sRS[tid]  = g_sq[rowBase + tid];
        sCSn[tid] = g_sq[colBase + tid];
        sRL[tid]  = g_lab[rowBase + tid];
        sCL[tid]  = g_lab[colBase + tid];
        sBP[tid]  = 0ULL;
        sBN[tid]  = 0xFFFFFFFFFFFFFFFFULL;
    }

    const uint32_t dynBase = smem_u32(dsm);
    const uint32_t aStage = dynBase;                        // + s*TILE_BYTES
    const uint32_t bStage = dynBase + NSTAGE * TILE_BYTES;  // + s*TILE_BYTES

    const __nv_bfloat16* srcA[3] = {g_Ehi, g_Ehi, g_Elo};
    const __nv_bfloat16* srcB[3] = {g_Ehi, g_Elo, g_Ehi};

    const int ldRow0 = tid >> 1;          // 2 threads per 64B row
    const int ldC0   = (tid & 1) * 2;     // each thread: 2 x 16B units

    float acc[4][4][4];
#pragma unroll
    for (int mi = 0; mi < 4; ++mi)
#pragma unroll
        for (int ni = 0; ni < 4; ++ni)
#pragma unroll
            for (int f = 0; f < 4; ++f) acc[mi][ni][f] = 0.f;

    auto loadChunk = [&](int kk, int stage) {
        int s  = kk >> 3;                 // segment (8 chunks of 32 each)
        int ko = (kk & 7) * BK;
        const __nv_bfloat16* A = srcA[s];
        const __nv_bfloat16* B = srcB[s];
        uint32_t aB = aStage + stage * TILE_BYTES;
        uint32_t bB = bStage + stage * TILE_BYTES;
#pragma unroll
        for (int i = 0; i < 2; ++i) {
            int c16 = ldC0 + i;           // 0..3
            cp16(aB + ldRow0 * ROWB + c16 * 16,
                 A + (size_t)(rowBase + ldRow0) * D + ko + c16 * 8);
            cp16(bB + ldRow0 * ROWB + c16 * 16,
                 B + (size_t)(colBase + ldRow0) * D + ko + c16 * 8);
        }
        CP_COMMIT();
    };

    loadChunk(0, 0);
    loadChunk(1, 1);

    for (int kk = 0; kk < NCHUNKS; ++kk) {
        if (kk + 1 < NCHUNKS) { CP_WAIT(1); } else { CP_WAIT(0); }
        __syncthreads();   // single barrier per chunk; bounds warp skew to <1 iter

        const int stage = kk % NSTAGE;
        const uint32_t aB = aStage + stage * TILE_BYTES;
        const uint32_t bB = bStage + stage * TILE_BYTES;

#pragma unroll
        for (int kh = 0; kh < BK; kh += 16) {
            uint32_t af[4][4];
#pragma unroll
            for (int mi = 0; mi < 4; ++mi) {
                int row = warpRow * 64 + mi * 16 + (lane & 15);
                int col = kh + ((lane >> 4) & 1) * 8;
                ldm_x4(af[mi][0], af[mi][1], af[mi][2], af[mi][3],
                       aB + row * ROWB + col * 2);
            }
            uint32_t bf[4][2];
#pragma unroll
            for (int pn = 0; pn < 2; ++pn) {
                int ntile = 2 * pn + ((lane >> 4) & 1);
                int krel  = kh + ((lane >> 3) & 1) * 8;
                int rowb  = warpCol * 32 + ntile * 8 + (lane & 7);
                uint32_t r0, r1, r2, r3;
                ldm_x4(r0, r1, r2, r3, bB + rowb * ROWB + krel * 2);
                bf[2 * pn][0] = r0; bf[2 * pn][1] = r1;
                bf[2 * pn + 1][0] = r2; bf[2 * pn + 1][1] = r3;
            }
#pragma unroll
            for (int mi = 0; mi < 4; ++mi)
#pragma unroll
                for (int ni = 0; ni < 4; ++ni)
                    mma_bf16(acc[mi][ni], af[mi], bf[ni]);
        }

        // prefetch chunk kk+2 into stage (kk+2)%3 = (kk-1)%3; every warp has
        // passed this iteration's barrier => all finished compute(kk-1).
        if (kk + 2 < NCHUNKS) loadChunk(kk + 2, (kk + 2) % NSTAGE);
    }
    __syncthreads();   // all compute done before mining reuses nothing, but
                       // guards sBP/sBN init visibility ordering below

    const int l4 = lane >> 2;   // 0..7 : row-in-8
    const int l2 = lane & 3;    // 0..3 : col pair

    // ---- phase 1: row-anchor mining (anchors = rowBase block) ----
    {
#pragma unroll
        for (int mi = 0; mi < 4; ++mi) {
#pragma unroll
            for (int h = 0; h < 2; ++h) {
                const int rloc = warpRow * 64 + mi * 16 + l4 + 8 * h;
                const int grow = rowBase + rloc;
                const float rs = sRS[rloc];
                const unsigned rl = sRL[rloc];
                unsigned long long bp = 0ULL, bn = 0xFFFFFFFFFFFFFFFFULL;
#pragma unroll
                for (int ni = 0; ni < 4; ++ni) {
#pragma unroll
                    for (int cc = 0; cc < 2; ++cc) {
                        const int cloc = warpCol * 32 + ni * 8 + 2 * l2 + cc;
                        const int gcol = colBase + cloc;
                        const unsigned cl = sCL[cloc];
                        float d2 = fmaxf(rs + sCSn[cloc]
                                         - 2.0f * acc[mi][ni][2 * h + cc], 0.0f);
                        if (rl == cl) {
                            if (grow != gcol) {
                                unsigned long long c = pack_p(d2, gcol);
                                if (c > bp) bp = c;
                            }
                        } else {
                            unsigned long long c = pack_n(d2, gcol);
                            if (c < bn) bn = c;
                        }
                    }
                }
#pragma unroll
                for (int o = 1; o <= 2; o <<= 1) {
                    unsigned long long op = __shfl_xor_sync(0xffffffffu, bp, o);
                    if (op > bp) bp = op;
                    unsigned long long on = __shfl_xor_sync(0xffffffffu, bn, o);
                    if (on < bn) bn = on;
                }
                if (l2 == 0) {
                    if (bp != 0ULL) atomicMax(&sBP[rloc], bp);
                    if (bn != 0xFFFFFFFFFFFFFFFFULL) atomicMin(&sBN[rloc], bn);
                }
            }
        }
        __syncthreads();
        if (tid < BM) {
            if (sBP[tid] != 0ULL) atomicMax(&g_hp[rowBase + tid], sBP[tid]);
            if (sBN[tid] != 0xFFFFFFFFFFFFFFFFULL) atomicMin(&g_hn[rowBase + tid], sBN[tid]);
        }
    }

    // ---- phase 2: col-anchor mining (anchors = colBase block), off-diag only
    if (offDiag) {
        __syncthreads();
        if (tid < BM) {
            sBP[tid] = 0ULL;
            sBN[tid] = 0xFFFFFFFFFFFFFFFFULL;
        }
        __syncthreads();

#pragma unroll
        for (int ni = 0; ni < 4; ++ni) {
#pragma unroll
            for (int cc = 0; cc < 2; ++cc) {
                const int cloc = warpCol * 32 + ni * 8 + 2 * l2 + cc;
                const float cs = sCSn[cloc];
                const unsigned cl = sCL[cloc];
                unsigned long long bp = 0ULL, bn = 0xFFFFFFFFFFFFFFFFULL;
#pragma unroll
                for (int mi = 0; mi < 4; ++mi) {
#pragma unroll
                    for (int h = 0; h < 2; ++h) {
                        const int rloc = warpRow * 64 + mi * 16 + l4 + 8 * h;
                        const int grow = rowBase + rloc;
                        const unsigned rl = sRL[rloc];
                        float d2 = fmaxf(cs + sRS[rloc]
                                         - 2.0f * acc[mi][ni][2 * h + cc], 0.0f);
                        if (cl == rl) {
                            // off-diagonal tile => grow != gcol always
                            unsigned long long c = pack_p(d2, grow);
                            if (c > bp) bp = c;
                        } else {
                            unsigned long long c = pack_n(d2, grow);
                            if (c < bn) bn = c;
                        }
                    }
                }
                // merge the 8 lanes sharing this col (lane bits 2..4)
#pragma unroll
                for (int o = 4; o <= 16; o <<= 1) {
                    unsigned long long op = __shfl_xor_sync(0xffffffffu, bp, o);
                    if (op > bp) bp = op;
                    unsigned long long on = __shfl_xor_sync(0xffffffffu, bn, o);
                    if (on < bn) bn = on;
                }
                if (l4 == 0) {
                    if (bp != 0ULL) atomicMax(&sBP[cloc], bp);
                    if (bn != 0xFFFFFFFFFFFFFFFFULL) atomicMin(&sBN[cloc], bn);
                }
            }
        }
        __syncthreads();
        if (tid < BM) {
            if (sBP[tid] != 0ULL) atomicMax(&g_hp[colBase + tid], sBP[tid]);
            if (sBN[tid] != 0xFFFFFFFFFFFFFFFFULL) atomicMin(&g_hn[colBase + tid], sBN[tid]);
        }
    }
}

// -------- kernel 2: per-anchor d_pn + triplet loss --------------------------
__global__ void k_loss(const float* __restrict__ E) {
    int warp = (blockIdx.x * blockDim.x + threadIdx.x) >> 5;
    int lane = threadIdx.x & 31;
    if (warp >= N) return;
    int i = warp;
    unsigned long long hp = g_hp[i], hn = g_hn[i];
    bool valid = (hp != 0ULL) && (hn != 0xFFFFFFFFFFFFFFFFULL);
    if (!valid) {
        if (lane == 0) { g_loss[i] = 0.f; g_nz[i] = 0; }
        return;
    }
    int   pi   = (int)(~(unsigned)hp) & (N - 1);
    float d2ap = __uint_as_float((unsigned)(hp >> 32));
    int   ni   = (int)((unsigned)hn);
    float d2an = __uint_as_float((unsigned)(hn >> 32));

    const float* P = E + (size_t)pi * D;
    const float* Q = E + (size_t)ni * D;
    float acc = 0.f;
#pragma unroll
    for (int t = 0; t < D / 32; ++t)
        acc = fmaf(P[lane + 32 * t], Q[lane + 32 * t], acc);
#pragma unroll
    for (int o = 16; o; o >>= 1) acc += __shfl_xor_sync(0xffffffffu, acc, o);

    if (lane == 0) {
        float d2pn = fmaxf(g_sq[pi] + g_sq[ni] - 2.0f * acc, 0.0f);
        float l = fmaxf(sqrtf(d2ap) - fminf(sqrtf(d2an), sqrtf(d2pn)) + MARGIN, 0.0f);
        bool nz = l > 0.0f;
        g_loss[i] = nz ? l : 0.0f;
        g_nz[i]   = nz ? 1 : 0;
    }
}

// -------- kernel 3: deterministic final reduction ---------------------------
__global__ void k_reduce(float* __restrict__ out) {
    __shared__ float ssum[256];
    __shared__ int   scnt[256];
    int tid = threadIdx.x;
    float s = 0.f; int c = 0;
    for (int i = tid; i < N; i += 256) { s += g_loss[i]; c += g_nz[i]; }
    ssum[tid] = s; scnt[tid] = c;
    __syncthreads();
    for (int o = 128; o; o >>= 1) {
        if (tid < o) { ssum[tid] += ssum[tid + o]; scnt[tid] += scnt[tid + o]; }
        __syncthreads();
    }
    if (tid == 0) {
        float cnt = (float)scnt[0];
        out[0] = (cnt > 0.f) ? (ssum[0] / fmaxf(cnt, 1.0f)) : 0.0f;
    }
}

extern "C" void kernel_launch(void* const* d_in, const int* in_sizes, int n_in,
                              void* d_out, int out_size) {
    const float* E  = (const float*)d_in[0];
    const unsigned char* pm = (const unsigned char*)d_in[1];
    const unsigned char* nm = (const unsigned char*)d_in[2];
    float* out = (float*)d_out;

    // idempotent, not a stream op — safe under graph capture
    cudaFuncSetAttribute(k_mine_mma, cudaFuncAttributeMaxDynamicSharedMemorySize, DYN_SMEM);

    k_labels<<<N / 8, 256>>>(pm, nm);
    k_prep<<<N / 8, 256>>>(E);
    k_mine_mma<<<NCTAS, 256, DYN_SMEM>>>();
    k_loss<<<N / 8, 256>>>(E);
    k_reduce<<<1, 256>>>(out);
}

// round 12
// speedup vs baseline: 1.2544x; 1.1306x over previous
#include <cuda_runtime.h>
#include <cuda_bf16.h>
#include <cstdint>

#define N 4096
#define D 256
#define MARGIN 0.2f

#define BM 128
#define BN 128
#define BK 32
#define NCHUNKS (D / BK)    // 8 (each chunk does all 3 split terms)
#define ROWB 80             // padded smem row bytes (32 bf16 = 64B + 16B pad)
#define NSTAGE 2
#define NTILE (N / BM)      // 32
#define NCTAS (NTILE * (NTILE + 1) / 2)  // 528

#define TILE_BYTES (BM * ROWB)               // 10240
#define STAGE_BYTES (4 * TILE_BYTES)         // Ah|Al|Bh|Bl = 40960
#define DYN_SMEM (NSTAGE * STAGE_BYTES)      // 81920

// ---------------- scratch (static device globals) ----------------
__device__ unsigned long long g_hp[N];   // (d2_bits<<32)|~idx, argmax (tie -> min idx)
__device__ unsigned long long g_hn[N];   // (d2_bits<<32)| idx, argmin (tie -> min idx)
__device__ float g_sq[N];
__device__ float g_loss[N];
__device__ int   g_nz[N];
__device__ unsigned short g_lab[N];      // class representative per row
__device__ __nv_bfloat16 g_Ehi[N * D];
__device__ __nv_bfloat16 g_Elo[N * D];

__device__ __forceinline__ unsigned long long pack_p(float v, int idx) {
    return (((unsigned long long)__float_as_uint(v)) << 32) | (unsigned)(~idx);
}
__device__ __forceinline__ unsigned long long pack_n(float v, int idx) {
    return (((unsigned long long)__float_as_uint(v)) << 32) | (unsigned)idx;
}

// ---------------- generic-PTX helpers (compute_103-safe) ----------------
__device__ __forceinline__ uint32_t smem_u32(const void* p) {
    uint32_t a;
    asm("{ .reg .u64 t; cvta.to.shared.u64 t, %1; cvt.u32.u64 %0, t; }" : "=r"(a) : "l"(p));
    return a;
}
__device__ __forceinline__ void cp16(uint32_t dst, const void* src) {
    asm volatile("cp.async.cg.shared.global [%0], [%1], 16;" :: "r"(dst), "l"(src));
}
#define CP_COMMIT() asm volatile("cp.async.commit_group;" ::: "memory")
#define CP_WAIT(n)  asm volatile("cp.async.wait_group %0;" :: "n"(n) : "memory")

__device__ __forceinline__ void ldm_x4(uint32_t& r0, uint32_t& r1, uint32_t& r2, uint32_t& r3,
                                       uint32_t addr) {
    asm volatile("ldmatrix.sync.aligned.m8n8.x4.shared.b16 {%0,%1,%2,%3}, [%4];"
                 : "=r"(r0), "=r"(r1), "=r"(r2), "=r"(r3) : "r"(addr));
}
__device__ __forceinline__ void mma_bf16(float* c, const uint32_t* a, const uint32_t* b) {
    asm volatile("mma.sync.aligned.m16n8k16.row.col.f32.bf16.bf16.f32 "
                 "{%0,%1,%2,%3}, {%4,%5,%6,%7}, {%8,%9}, {%0,%1,%2,%3};"
                 : "+f"(c[0]), "+f"(c[1]), "+f"(c[2]), "+f"(c[3])
                 : "r"(a[0]), "r"(a[1]), "r"(a[2]), "r"(a[3]), "r"(b[0]), "r"(b[1]));
}

// -------- kernel L: reconstruct class representatives from positives_mask ---
// Masks are label-derived (pos = same&~eye, neg = ~same), so pos is an
// equivalence relation minus the diagonal. rep[i] = min(i, first j with
// pos[i][j]) resolves to the minimum member of i's class for every member.
// Then pos(i,j) == (rep[i]==rep[j] && i!=j), neg(i,j) == (rep[i]!=rep[j]).
__global__ void k_labels(const unsigned char* __restrict__ pm,
                         const unsigned char* __restrict__ nm) {
    // dtype probe: element (0,1) is set in exactly one of pos/neg. u8 layout ->
    // byte 1 nonzero in one; i32 layout -> byte 1 is a zero high-byte in both.
    const bool is_u8 = ((pm[1] | nm[1]) != 0);
    int row = (blockIdx.x * blockDim.x + threadIdx.x) >> 5;
    int lane = threadIdx.x & 31;
    if (row >= N) return;
    int first = N;
    if (is_u8) {
        const unsigned char* prow = pm + (size_t)row * N;
        for (int base = 0; base < N; base += 32) {
            unsigned m = __ballot_sync(0xffffffffu, prow[base + lane] != 0);
            if (m) { first = base + __ffs(m) - 1; break; }
        }
    } else {
        const int* prow = (const int*)pm + (size_t)row * N;
        for (int base = 0; base < N; base += 32) {
            unsigned m = __ballot_sync(0xffffffffu, prow[base + lane] != 0);
            if (m) { first = base + __ffs(m) - 1; break; }
        }
    }
    if (lane == 0) g_lab[row] = (unsigned short)min(row, first);
}

// -------- kernel R: bf16 split + sq norms + scratch init (one pass) ---------
__global__ void k_prep(const float* __restrict__ E) {
    int warp = (blockIdx.x * blockDim.x + threadIdx.x) >> 5;
    int lane = threadIdx.x & 31;
    if (warp >= N) return;
    const float* row = E + (size_t)warp * D;
    __nv_bfloat16* hiRow = g_Ehi + (size_t)warp * D;
    __nv_bfloat16* loRow = g_Elo + (size_t)warp * D;
    float acc = 0.f;
#pragma unroll
    for (int t = 0; t < D / 32; ++t) {
        float v = row[lane + 32 * t];
        __nv_bfloat16 hi = __float2bfloat16(v);
        __nv_bfloat16 lo = __float2bfloat16(v - __bfloat162float(hi));
        hiRow[lane + 32 * t] = hi;
        loRow[lane + 32 * t] = lo;
        acc = fmaf(v, v, acc);
    }
#pragma unroll
    for (int o = 16; o; o >>= 1) acc += __shfl_xor_sync(0xffffffffu, acc, o);
    if (lane == 0) {
        g_sq[warp] = acc;
        g_hp[warp] = 0ULL;
        g_hn[warp] = 0xFFFFFFFFFFFFFFFFULL;
    }
}

// -------- kernel 1: bf16-split HMMA Gram tile + symmetric label mining ------
// 528 CTAs: upper-triangular tiles (bx<=by). Each 32-wide K-chunk loads
// A_hi/A_lo/B_hi/B_lo once and issues all three split terms
// (H.H^T + H.L^T + L.H^T) from shared operands. Double-buffered, one
// __syncthreads per chunk (8 total). Stage layout: [Ah|Al|Bh|Bl].
__global__ void __launch_bounds__(256, 2) k_mine_mma() {
    extern __shared__ __align__(16) char dsm[];
    __shared__ float sRS[BM];
    __shared__ float sCSn[BN];
    __shared__ unsigned short sRL[BM];
    __shared__ unsigned short sCL[BN];
    __shared__ unsigned long long sBP[BM];
    __shared__ unsigned long long sBN[BM];

    const int tid = threadIdx.x;
    const int wid = tid >> 5;
    const int lane = tid & 31;
    const int warpRow = wid >> 2;        // 0..1  (64 rows each)
    const int warpCol = wid & 3;         // 0..3  (32 cols each)

    // triangular tile decode: tile t -> (bx, by), by >= bx
    int bx = 0, rem = blockIdx.x;
    while (rem >= NTILE - bx) { rem -= NTILE - bx; ++bx; }
    const int by = bx + rem;
    const int rowBase = bx * BM;
    const int colBase = by * BN;
    const bool offDiag = (bx != by);

    if (tid < BM) {
        sRS[tid]  = g_sq[rowBase + tid];
        sCSn[tid] = g_sq[colBase + tid];
        sRL[tid]  = g_lab[rowBase + tid];
        sCL[tid]  = g_lab[colBase + tid];
        sBP[tid]  = 0ULL;
        sBN[tid]  = 0xFFFFFFFFFFFFFFFFULL;
    }

    const uint32_t dynBase = smem_u32(dsm);

    const int ldRow0 = tid >> 1;          // 2 threads per 64B row
    const int ldC0   = (tid & 1) * 2;     // each thread: 2 x 16B units per tile

    float acc[4][4][4];
#pragma unroll
    for (int mi = 0; mi < 4; ++mi)
#pragma unroll
        for (int ni = 0; ni < 4; ++ni)
#pragma unroll
            for (int f = 0; f < 4; ++f) acc[mi][ni][f] = 0.f;

    auto loadChunk = [&](int kk, int stage) {
        const int ko = kk * BK;
        const uint32_t sb = dynBase + stage * STAGE_BYTES;
        const uint32_t dstRow = sb + ldRow0 * ROWB;
        const __nv_bfloat16* ah = g_Ehi + (size_t)(rowBase + ldRow0) * D + ko;
        const __nv_bfloat16* al = g_Elo + (size_t)(rowBase + ldRow0) * D + ko;
        const __nv_bfloat16* bh = g_Ehi + (size_t)(colBase + ldRow0) * D + ko;
        const __nv_bfloat16* bl = g_Elo + (size_t)(colBase + ldRow0) * D + ko;
#pragma unroll
        for (int i = 0; i < 2; ++i) {
            int c16 = ldC0 + i;           // 0..3
            cp16(dstRow + 0 * TILE_BYTES + c16 * 16, ah + c16 * 8);
            cp16(dstRow + 1 * TILE_BYTES + c16 * 16, al + c16 * 8);
            cp16(dstRow + 2 * TILE_BYTES + c16 * 16, bh + c16 * 8);
            cp16(dstRow + 3 * TILE_BYTES + c16 * 16, bl + c16 * 8);
        }
        CP_COMMIT();
    };

    loadChunk(0, 0);

    for (int kk = 0; kk < NCHUNKS; ++kk) {
        CP_WAIT(0);
        __syncthreads();   // every warp finished compute(kk-1) before the
                           // prefetch below overwrites its stage

        if (kk + 1 < NCHUNKS) loadChunk(kk + 1, (kk + 1) & 1);

        const uint32_t sb = dynBase + (kk & 1) * STAGE_BYTES;
        const uint32_t aHi = sb;
        const uint32_t aLo = sb + TILE_BYTES;
        const uint32_t bHi = sb + 2 * TILE_BYTES;
        const uint32_t bLo = sb + 3 * TILE_BYTES;

#pragma unroll
        for (int kh = 0; kh < BK; kh += 16) {
            const int arow = warpRow * 64 + (lane & 15);
            const int acol = (kh + ((lane >> 4) & 1) * 8) * 2;
            const int krel = kh + ((lane >> 3) & 1) * 8;

            // B fragments (hi + lo), reused across two A passes
            uint32_t bfh[4][2], bfl[4][2];
#pragma unroll
            for (int pn = 0; pn < 2; ++pn) {
                int rowb = warpCol * 32 + (2 * pn + ((lane >> 4) & 1)) * 8 + (lane & 7);
                uint32_t r0, r1, r2, r3;
                ldm_x4(r0, r1, r2, r3, bHi + rowb * ROWB + krel * 2);
                bfh[2 * pn][0] = r0; bfh[2 * pn][1] = r1;
                bfh[2 * pn + 1][0] = r2; bfh[2 * pn + 1][1] = r3;
                ldm_x4(r0, r1, r2, r3, bLo + rowb * ROWB + krel * 2);
                bfl[2 * pn][0] = r0; bfl[2 * pn][1] = r1;
                bfl[2 * pn + 1][0] = r2; bfl[2 * pn + 1][1] = r3;
            }

            // pass 1+2: A_hi x (B_hi, B_lo)
            {
                uint32_t af[4][4];
#pragma unroll
                for (int mi = 0; mi < 4; ++mi)
                    ldm_x4(af[mi][0], af[mi][1], af[mi][2], af[mi][3],
                           aHi + (arow + mi * 16) * ROWB + acol);
#pragma unroll
                for (int mi = 0; mi < 4; ++mi)
#pragma unroll
                    for (int ni = 0; ni < 4; ++ni) {
                        mma_bf16(acc[mi][ni], af[mi], bfh[ni]);
                        mma_bf16(acc[mi][ni], af[mi], bfl[ni]);
                    }
            }
            // pass 3: A_lo x B_hi
            {
                uint32_t af[4][4];
#pragma unroll
                for (int mi = 0; mi < 4; ++mi)
                    ldm_x4(af[mi][0], af[mi][1], af[mi][2], af[mi][3],
                           aLo + (arow + mi * 16) * ROWB + acol);
#pragma unroll
                for (int mi = 0; mi < 4; ++mi)
#pragma unroll
                    for (int ni = 0; ni < 4; ++ni)
                        mma_bf16(acc[mi][ni], af[mi], bfh[ni]);
            }
        }
    }
    __syncthreads();   // orders sBP/sBN init + compute completion before mining

    const int l4 = lane >> 2;   // 0..7 : row-in-8
    const int l2 = lane & 3;    // 0..3 : col pair

    // ---- phase 1: row-anchor mining (anchors = rowBase block) ----
    {
#pragma unroll
        for (int mi = 0; mi < 4; ++mi) {
#pragma unroll
            for (int h = 0; h < 2; ++h) {
                const int rloc = warpRow * 64 + mi * 16 + l4 + 8 * h;
                const int grow = rowBase + rloc;
                const float rs = sRS[rloc];
                const unsigned rl = sRL[rloc];
                unsigned long long bp = 0ULL, bn = 0xFFFFFFFFFFFFFFFFULL;
#pragma unroll
                for (int ni = 0; ni < 4; ++ni) {
#pragma unroll
                    for (int cc = 0; cc < 2; ++cc) {
                        const int cloc = warpCol * 32 + ni * 8 + 2 * l2 + cc;
                        const int gcol = colBase + cloc;
                        const unsigned cl = sCL[cloc];
                        float d2 = fmaxf(rs + sCSn[cloc]
                                         - 2.0f * acc[mi][ni][2 * h + cc], 0.0f);
                        if (rl == cl) {
                            if (grow != gcol) {
                                unsigned long long c = pack_p(d2, gcol);
                                if (c > bp) bp = c;
                            }
                        } else {
                            unsigned long long c = pack_n(d2, gcol);
                            if (c < bn) bn = c;
                        }
                    }
                }
#pragma unroll
                for (int o = 1; o <= 2; o <<= 1) {
                    unsigned long long op = __shfl_xor_sync(0xffffffffu, bp, o);
                    if (op > bp) bp = op;
                    unsigned long long on = __shfl_xor_sync(0xffffffffu, bn, o);
                    if (on < bn) bn = on;
                }
                if (l2 == 0) {
                    if (bp != 0ULL) atomicMax(&sBP[rloc], bp);
                    if (bn != 0xFFFFFFFFFFFFFFFFULL) atomicMin(&sBN[rloc], bn);
                }
            }
        }
        __syncthreads();
        if (tid < BM) {
            if (sBP[tid] != 0ULL) atomicMax(&g_hp[rowBase + tid], sBP[tid]);
            if (sBN[tid] != 0xFFFFFFFFFFFFFFFFULL) atomicMin(&g_hn[rowBase + tid], sBN[tid]);
        }
    }

    // ---- phase 2: col-anchor mining (anchors = colBase block), off-diag only
    if (offDiag) {
        __syncthreads();
        if (tid < BM) {
            sBP[tid] = 0ULL;
            sBN[tid] = 0xFFFFFFFFFFFFFFFFULL;
        }
        __syncthreads();

#pragma unroll
        for (int ni = 0; ni < 4; ++ni) {
#pragma unroll
            for (int cc = 0; cc < 2; ++cc) {
                const int cloc = warpCol * 32 + ni * 8 + 2 * l2 + cc;
                const float cs = sCSn[cloc];
                const unsigned cl = sCL[cloc];
                unsigned long long bp = 0ULL, bn = 0xFFFFFFFFFFFFFFFFULL;
#pragma unroll
                for (int mi = 0; mi < 4; ++mi) {
#pragma unroll
                    for (int h = 0; h < 2; ++h) {
                        const int rloc = warpRow * 64 + mi * 16 + l4 + 8 * h;
                        const int grow = rowBase + rloc;
                        const unsigned rl = sRL[rloc];
                        float d2 = fmaxf(cs + sRS[rloc]
                                         - 2.0f * acc[mi][ni][2 * h + cc], 0.0f);
                        if (cl == rl) {
                            // off-diagonal tile => grow != gcol always
                            unsigned long long c = pack_p(d2, grow);
                            if (c > bp) bp = c;
                        } else {
                            unsigned long long c = pack_n(d2, grow);
                            if (c < bn) bn = c;
                        }
                    }
                }
                // merge the 8 lanes sharing this col (lane bits 2..4)
#pragma unroll
                for (int o = 4; o <= 16; o <<= 1) {
                    unsigned long long op = __shfl_xor_sync(0xffffffffu, bp, o);
                    if (op > bp) bp = op;
                    unsigned long long on = __shfl_xor_sync(0xffffffffu, bn, o);
                    if (on < bn) bn = on;
                }
                if (l4 == 0) {
                    if (bp != 0ULL) atomicMax(&sBP[cloc], bp);
                    if (bn != 0xFFFFFFFFFFFFFFFFULL) atomicMin(&sBN[cloc], bn);
                }
            }
        }
        __syncthreads();
        if (tid < BM) {
            if (sBP[tid] != 0ULL) atomicMax(&g_hp[colBase + tid], sBP[tid]);
            if (sBN[tid] != 0xFFFFFFFFFFFFFFFFULL) atomicMin(&g_hn[colBase + tid], sBN[tid]);
        }
    }
}

// -------- kernel 2: per-anchor d_pn + triplet loss --------------------------
__global__ void k_loss(const float* __restrict__ E) {
    int warp = (blockIdx.x * blockDim.x + threadIdx.x) >> 5;
    int lane = threadIdx.x & 31;
    if (warp >= N) return;
    int i = warp;
    unsigned long long hp = g_hp[i], hn = g_hn[i];
    bool valid = (hp != 0ULL) && (hn != 0xFFFFFFFFFFFFFFFFULL);
    if (!valid) {
        if (lane == 0) { g_loss[i] = 0.f; g_nz[i] = 0; }
        return;
    }
    int   pi   = (int)(~(unsigned)hp) & (N - 1);
    float d2ap = __uint_as_float((unsigned)(hp >> 32));
    int   ni   = (int)((unsigned)hn);
    float d2an = __uint_as_float((unsigned)(hn >> 32));

    const float* P = E + (size_t)pi * D;
    const float* Q = E + (size_t)ni * D;
    float acc = 0.f;
#pragma unroll
    for (int t = 0; t < D / 32; ++t)
        acc = fmaf(P[lane + 32 * t], Q[lane + 32 * t], acc);
#pragma unroll
    for (int o = 16; o; o >>= 1) acc += __shfl_xor_sync(0xffffffffu, acc, o);

    if (lane == 0) {
        float d2pn = fmaxf(g_sq[pi] + g_sq[ni] - 2.0f * acc, 0.0f);
        float l = fmaxf(sqrtf(d2ap) - fminf(sqrtf(d2an), sqrtf(d2pn)) + MARGIN, 0.0f);
        bool nz = l > 0.0f;
        g_loss[i] = nz ? l : 0.0f;
        g_nz[i]   = nz ? 1 : 0;
    }
}

// -------- kernel 3: deterministic final reduction ---------------------------
__global__ void k_reduce(float* __restrict__ out) {
    __shared__ float ssum[256];
    __shared__ int   scnt[256];
    int tid = threadIdx.x;
    float s = 0.f; int c = 0;
    for (int i = tid; i < N; i += 256) { s += g_loss[i]; c += g_nz[i]; }
    ssum[tid] = s; scnt[tid] = c;
    __syncthreads();
    for (int o = 128; o; o >>= 1) {
        if (tid < o) { ssum[tid] += ssum[tid + o]; scnt[tid] += scnt[tid + o]; }
        __syncthreads();
    }
    if (tid == 0) {
        float cnt = (float)scnt[0];
        out[0] = (cnt > 0.f) ? (ssum[0] / fmaxf(cnt, 1.0f)) : 0.0f;
    }
}

extern "C" void kernel_launch(void* const* d_in, const int* in_sizes, int n_in,
                              void* d_out, int out_size) {
    const float* E  = (const float*)d_in[0];
    const unsigned char* pm = (const unsigned char*)d_in[1];
    const unsigned char* nm = (const unsigned char*)d_in[2];
    float* out = (float*)d_out;

    // idempotent, not a stream op — safe under graph capture
    cudaFuncSetAttribute(k_mine_mma, cudaFuncAttributeMaxDynamicSharedMemorySize, DYN_SMEM);

    k_labels<<<N / 8, 256>>>(pm, nm);
    k_prep<<<N / 8, 256>>>(E);
    k_mine_mma<<<NCTAS, 256, DYN_SMEM>>>();
    k_loss<<<N / 8, 256>>>(E);
    k_reduce<<<1, 256>>>(out);
}